// round 5
// baseline (speedup 1.0000x reference)
#include <cuda_runtime.h>
#include <cstdint>
typedef unsigned long long ull;

#define TT 128
#define AD 8
#define ZD 32
#define KG4 74
#define KGP 300   // padded xh row stride (floats)
#define UD 128
#define US 132    // padded u row stride
#define CL 4
#define NT 512

#define XH_F 0                    // [2][32][KGP]
#define U1_F 19200
#define U2_F (U1_F + 8*US)
#define ZZ_F (U2_F + 8*US)
#define MB_B ((ZZ_F + 512) * 4)   // hbar @ +0, zbar @ +8
#define SMEM_B (MB_B + 16)

__device__ __align__(16) float Wg_perm[KG4 * 1024 * 4];
__device__ __align__(16) float W1_perm[64 * 128 * 4];
__device__ __align__(16) float W2_perm[32 * 128 * 4];
__device__ __align__(16) float Wz_perm[32 * 64 * 4];

__device__ __forceinline__ void fma2(ull &d, ull a, ull b) {
    asm("fma.rn.f32x2 %0, %1, %2, %0;" : "+l"(d) : "l"(a), "l"(b));
}
__device__ __forceinline__ float hsum2(ull v) {
    float lo, hi; asm("mov.b64 {%0, %1}, %2;" : "=f"(lo), "=f"(hi) : "l"(v));
    return lo + hi;
}
__device__ __forceinline__ float fsig(float x) { return 1.f / (1.f + __expf(-x)); }
__device__ __forceinline__ float ftanh_(float x) { return fmaf(2.f, fsig(2.f * x), -1.f); }
__device__ __forceinline__ uint32_t smem_u32(const void* p) {
    uint32_t a;
    asm("{ .reg .u64 t; cvta.to.shared.u64 t, %1; cvt.u32.u64 %0, t; }" : "=r"(a) : "l"(p));
    return a;
}
__device__ __forceinline__ uint32_t ctarank() {
    uint32_t r; asm("mov.u32 %0, %%cluster_ctarank;" : "=r"(r)); return r;
}
__device__ __forceinline__ uint32_t mapa_(uint32_t a, uint32_t rk) {
    uint32_t r; asm("mapa.shared::cluster.u32 %0, %1, %2;" : "=r"(r) : "r"(a), "r"(rk));
    return r;
}
__device__ __forceinline__ void stc(uint32_t a, float v) {
    asm volatile("st.shared::cluster.f32 [%0], %1;" :: "r"(a), "f"(v) : "memory");
}
__device__ __forceinline__ void mbar_init(uint32_t m, uint32_t c) {
    asm volatile("mbarrier.init.shared.b64 [%0], %1;" :: "r"(m), "r"(c) : "memory");
}
__device__ __forceinline__ void mbar_arrive(uint32_t a) {
    asm volatile("mbarrier.arrive.release.cluster.shared::cluster.b64 _, [%0];"
                 :: "r"(a) : "memory");
}
__device__ __forceinline__ void mbar_wait(uint32_t a, uint32_t p) {
    asm volatile(
        "{\n\t.reg .pred P;\n\t"
        "W_%=:\n\t"
        "mbarrier.try_wait.parity.acquire.cluster.shared::cta.b64 P, [%0], %1, 0x989680;\n\t"
        "@P bra.uni D_%=;\n\t"
        "bra.uni W_%=;\n\t"
        "D_%=:\n\t}" :: "r"(a), "r"(p) : "memory");
}

__global__ void permute_weights(const float* __restrict__ W_ih, const float* __restrict__ W_hh,
                                const float* __restrict__ W1, const float* __restrict__ W2,
                                const float* __restrict__ Wz)
{
    const int stride = gridDim.x * blockDim.x;
    const int tid = blockIdx.x * blockDim.x + threadIdx.x;
    // band layout: row rr = rank*256 + g*64 + Rg  ->  global gate row g*256 + rank*64 + Rg
    for (int i = tid; i < KG4 * 1024 * 4; i += stride) {
        int j = i & 3, rr = (i >> 2) & 1023, k4 = i >> 12;
        int rank = rr >> 8, r = rr & 255;
        int G = ((r >> 6) << 8) + (rank << 6) + (r & 63);
        int k = 4 * k4 + j;
        Wg_perm[i] = (k < 40) ? W_ih[G * 40 + k] : W_hh[G * 256 + (k - 40)];
    }
    for (int i = tid; i < 64 * 128 * 4; i += stride) {
        int j = i & 3, m = (i >> 2) & 127, k4 = i >> 9;
        W1_perm[i] = W1[m * 256 + 4 * k4 + j];
    }
    for (int i = tid; i < 32 * 128 * 4; i += stride) {
        int j = i & 3, m = (i >> 2) & 127, k4 = i >> 9;
        W2_perm[i] = W2[m * 128 + 4 * k4 + j];
    }
    for (int i = tid; i < 32 * 64 * 4; i += stride) {
        int j = i & 3, m = (i >> 2) & 63, k4 = i >> 8;
        Wz_perm[i] = Wz[m * 128 + 4 * k4 + j];
    }
}

__global__ void __launch_bounds__(NT, 1) __cluster_dims__(CL, 1, 1)
lstm_guide_kernel(const float* __restrict__ A, const float* __restrict__ eps,
                  const float* __restrict__ z0, const float* __restrict__ h0,
                  const float* __restrict__ c0, const float* __restrict__ b_ih,
                  const float* __restrict__ b_hh, const float* __restrict__ b1,
                  const float* __restrict__ b2, const float* __restrict__ bz,
                  float* __restrict__ Z)
{
    extern __shared__ __align__(16) float smf[];
    float* xh  = smf + XH_F;   // cols: a 0..7 | z 8..39 | h 40..295
    float* u1s = smf + U1_F;
    float* u2s = smf + U2_F;
    float* zzs = smf + ZZ_F;

    const int tid = threadIdx.x;
    const uint32_t rank = ctarank();
    const int n0c = (blockIdx.x >> 2) * 32;
    const int Rg = tid >> 3, bg = tid & 7;
    const int hidG = 64 * (int)rank + Rg;

    const uint32_t smem0 = smem_u32(smf);
    const uint32_t hbar = smem0 + MB_B, zbar = smem0 + MB_B + 8;

    // hoisted remote addresses
    uint32_t xm[2][CL], hb[CL], zb[CL];
    #pragma unroll
    for (int g = 0; g < CL; ++g) {
        xm[0][g] = mapa_(smem0 + XH_F * 4, g);
        xm[1][g] = mapa_(smem0 + (XH_F + 32 * KGP) * 4, g);
        hb[g] = mapa_(hbar, g);
        zb[g] = mapa_(zbar, g);
    }

    const float bs0 = b_ih[hidG]       + b_hh[hidG];
    const float bs1 = b_ih[256 + hidG] + b_hh[256 + hidG];
    const float bs2 = b_ih[512 + hidG] + b_hh[512 + hidG];
    const float bs3 = b_ih[768 + hidG] + b_hh[768 + hidG];
    const float b1v = b1[tid >> 2], b2v = b2[tid >> 2], bzv = bz[tid >> 3];

    if (tid == 0) { mbar_init(hbar, CL * NT); mbar_init(zbar, CL * 256); }

    for (int i = tid; i < 32 * 256; i += NT) {          // h0
        int b = i >> 8, k = i & 255;
        xh[b * KGP + 40 + k] = h0[k];
    }
    for (int i = tid; i < 32 * ZD; i += NT) {           // z0
        int b = i >> 5, j = i & 31;
        xh[b * KGP + 8 + j] = z0[j];
    }
    if (tid < 256) {                                    // a_0
        int b = tid >> 3, k = tid & 7;
        xh[b * KGP + k] = A[((n0c + b) * TT) * AD + k];
    }
    float c_reg[4];
    #pragma unroll
    for (int j = 0; j < 4; ++j) c_reg[j] = c0[hidG];

    __syncthreads();
    asm volatile("barrier.cluster.arrive.aligned;" ::: "memory");
    asm volatile("barrier.cluster.wait.aligned;" ::: "memory");

    const float* wb = Wg_perm + ((int)rank * 256 + Rg) * 4;

    for (int t = 0; t < TT; ++t) {
        const uint32_t par = t & 1;
        const int cb = t & 1, nb = (t + 1) & 1;
        float* xh_p = xh + cb * 32 * KGP;
        float* xh_n = xh + nb * 32 * KGP;

        // ===== gates: 4 gate rows (i,f,g,o) of hidG  x  4 batch rows =====
        ull acc[4][4];
        #pragma unroll
        for (int g = 0; g < 4; ++g)
            #pragma unroll
            for (int j = 0; j < 4; ++j) acc[g][j] = 0ull;

        #pragma unroll 2
        for (int k4 = 0; k4 < KG4; ++k4) {
            const ulonglong2 w0 = __ldg((const ulonglong2*)(wb + (k4 * 1024 +   0) * 4));
            const ulonglong2 w1 = __ldg((const ulonglong2*)(wb + (k4 * 1024 +  64) * 4));
            const ulonglong2 w2 = __ldg((const ulonglong2*)(wb + (k4 * 1024 + 128) * 4));
            const ulonglong2 w3 = __ldg((const ulonglong2*)(wb + (k4 * 1024 + 192) * 4));
            #pragma unroll
            for (int j = 0; j < 4; ++j) {
                const ulonglong2 xv = *(const ulonglong2*)(xh_p + (bg + 8 * j) * KGP + 4 * k4);
                fma2(acc[0][j], w0.x, xv.x); fma2(acc[0][j], w0.y, xv.y);
                fma2(acc[1][j], w1.x, xv.x); fma2(acc[1][j], w1.y, xv.y);
                fma2(acc[2][j], w2.x, xv.x); fma2(acc[2][j], w2.y, xv.y);
                fma2(acc[3][j], w3.x, xv.x); fma2(acc[3][j], w3.y, xv.y);
            }
        }

        // ===== LSTM cell, all gates in-thread =====
        float hv[4];
        #pragma unroll
        for (int j = 0; j < 4; ++j) {
            float iv = fsig(hsum2(acc[0][j]) + bs0);
            float fv = fsig(hsum2(acc[1][j]) + bs1);
            float gv = ftanh_(hsum2(acc[2][j]) + bs2);
            float ov = fsig(hsum2(acc[3][j]) + bs3);
            float c = fv * c_reg[j] + iv * gv;
            c_reg[j] = c;
            hv[j] = ov * ftanh_(c);
        }

        // ===== h broadcast to all 4 CTAs' next xh =====
        {
            const uint32_t hoff = (uint32_t)(40 + hidG) * 4;
            #pragma unroll
            for (int g = 0; g < CL; ++g) {
                const uint32_t base = xm[nb][g] + hoff;
                #pragma unroll
                for (int j = 0; j < 4; ++j)
                    stc(base + (uint32_t)((bg + 8 * j) * KGP) * 4, hv[j]);
            }
            #pragma unroll
            for (int g = 0; g < CL; ++g) mbar_arrive(hb[g]);
        }

        if (tid < 256 && t + 1 < TT) {                  // a_{t+1} prefetch (local)
            int b = tid >> 3, k = tid & 7;
            xh_n[b * KGP + k] = A[((n0c + b) * TT + t + 1) * AD + k];
        }

        mbar_wait(hbar, par);
        __syncthreads();

        // ===== MLP1: relu(h_{t+1} @ W1^T + b1), own 8 batch rows =====
        {
            const int m = tid >> 2, bq = tid & 3;
            const float* x0 = xh_n + (8 * (int)rank + bq) * KGP + 40;
            const float* x1 = x0 + 4 * KGP;
            ull a0 = 0ull, a1 = 0ull;
            #pragma unroll 4
            for (int k4 = 0; k4 < 64; ++k4) {
                const ulonglong2 wv = __ldg((const ulonglong2*)(W1_perm + ((k4 << 7) + m) * 4));
                const ulonglong2 p0 = *(const ulonglong2*)(x0 + 4 * k4);
                const ulonglong2 p1 = *(const ulonglong2*)(x1 + 4 * k4);
                fma2(a0, wv.x, p0.x); fma2(a0, wv.y, p0.y);
                fma2(a1, wv.x, p1.x); fma2(a1, wv.y, p1.y);
            }
            u1s[bq * US + m]       = fmaxf(hsum2(a0) + b1v, 0.f);
            u1s[(bq + 4) * US + m] = fmaxf(hsum2(a1) + b1v, 0.f);
        }
        __syncthreads();

        // ===== MLP2 =====
        {
            const int m = tid >> 2, bq = tid & 3;
            const float* x0 = u1s + bq * US;
            const float* x1 = x0 + 4 * US;
            ull a0 = 0ull, a1 = 0ull;
            #pragma unroll 4
            for (int k4 = 0; k4 < 32; ++k4) {
                const ulonglong2 wv = __ldg((const ulonglong2*)(W2_perm + ((k4 << 7) + m) * 4));
                const ulonglong2 p0 = *(const ulonglong2*)(x0 + 4 * k4);
                const ulonglong2 p1 = *(const ulonglong2*)(x1 + 4 * k4);
                fma2(a0, wv.x, p0.x); fma2(a0, wv.y, p0.y);
                fma2(a1, wv.x, p1.x); fma2(a1, wv.y, p1.y);
            }
            u2s[bq * US + m]       = fmaxf(hsum2(a0) + b2v, 0.f);
            u2s[(bq + 4) * US + m] = fmaxf(hsum2(a1) + b2v, 0.f);
        }
        __syncthreads();

        // ===== zz = u2 @ Wz^T + bz =====
        {
            const int jz = tid >> 3, rz = tid & 7;
            const float* xp = u2s + rz * US;
            ull a0 = 0ull;
            #pragma unroll 4
            for (int k4 = 0; k4 < 32; ++k4) {
                const ulonglong2 wv = __ldg((const ulonglong2*)(Wz_perm + ((k4 << 6) + jz) * 4));
                const ulonglong2 pv = *(const ulonglong2*)(xp + 4 * k4);
                fma2(a0, wv.x, pv.x); fma2(a0, wv.y, pv.y);
            }
            zzs[rz * 64 + jz] = hsum2(a0) + bzv;
        }
        __syncthreads();

        // ===== z_t = loc + softplus(raw) * eps; broadcast to cluster =====
        if (tid < 256) {
            const int j = tid & 31, rr = tid >> 5;
            const int bown = 8 * (int)rank + rr;
            float loc = zzs[rr * 64 + j];
            float sr  = zzs[rr * 64 + 32 + j];
            float sp  = (sr > 15.f) ? sr : log1pf(__expf(sr));
            float e   = eps[((n0c + bown) * TT + t) * ZD + j];
            float zn  = fmaf(sp, e, loc);
            Z[((n0c + bown) * TT + t) * ZD + j] = zn;
            const uint32_t zoff = (uint32_t)((bown * KGP + 8 + j) * 4);
            #pragma unroll
            for (int g = 0; g < CL; ++g) stc(xm[nb][g] + zoff, zn);
            #pragma unroll
            for (int g = 0; g < CL; ++g) mbar_arrive(zb[g]);
        }
        mbar_wait(zbar, par);
        __syncthreads();
    }
}

extern "C" void kernel_launch(void* const* d_in, const int* in_sizes, int n_in,
                              void* d_out, int out_size) {
    const float* A    = (const float*)d_in[0];
    const float* eps  = (const float*)d_in[1];
    const float* z0   = (const float*)d_in[2];
    const float* h0   = (const float*)d_in[3];
    const float* c0   = (const float*)d_in[4];
    const float* W_ih = (const float*)d_in[5];
    const float* W_hh = (const float*)d_in[6];
    const float* b_ih = (const float*)d_in[7];
    const float* b_hh = (const float*)d_in[8];
    const float* W1   = (const float*)d_in[9];
    const float* b1   = (const float*)d_in[10];
    const float* W2   = (const float*)d_in[11];
    const float* b2   = (const float*)d_in[12];
    const float* Wz   = (const float*)d_in[13];
    const float* bz   = (const float*)d_in[14];

    static int smem_set = 0;
    if (!smem_set) {
        cudaFuncSetAttribute(lstm_guide_kernel,
                             cudaFuncAttributeMaxDynamicSharedMemorySize, SMEM_B);
        smem_set = 1;
    }
    permute_weights<<<148, 256>>>(W_ih, W_hh, W1, W2, Wz);
    lstm_guide_kernel<<<128, NT, SMEM_B>>>(A, eps, z0, h0, c0,
                                           b_ih, b_hh, b1, b2, bz, (float*)d_out);
}

// round 6
// speedup vs baseline: 1.0472x; 1.0472x over previous
#include <cuda_runtime.h>
#include <cstdint>
typedef unsigned long long ull;

#define TT 128
#define AD 8
#define ZD 32
#define KG4 74
#define KGP 300   // padded xh row stride (floats)
#define US 132    // padded u row stride
#define CL 4
#define NT 512

#define XH_F 0                    // [2][32][KGP]
#define U1_F 19200
#define U2_F (U1_F + 8*US)
#define ZZ_F (U2_F + 8*US)
#define SMEM_B ((ZZ_F + 512) * 4)

__device__ __align__(16) float Wg_perm[KG4 * 1024 * 4];
__device__ __align__(16) float W1_perm[64 * 128 * 4];
__device__ __align__(16) float W2_perm[32 * 128 * 4];
__device__ __align__(16) float Wz_perm[32 * 64 * 4];

__device__ __forceinline__ void fma2(ull &d, ull a, ull b) {
    asm("fma.rn.f32x2 %0, %1, %2, %0;" : "+l"(d) : "l"(a), "l"(b));
}
__device__ __forceinline__ float hsum2(ull v) {
    float lo, hi; asm("mov.b64 {%0, %1}, %2;" : "=f"(lo), "=f"(hi) : "l"(v));
    return lo + hi;
}
__device__ __forceinline__ float fsig(float x) { return 1.f / (1.f + __expf(-x)); }
__device__ __forceinline__ float ftanh_(float x) { return fmaf(2.f, fsig(2.f * x), -1.f); }
__device__ __forceinline__ uint32_t smem_u32(const void* p) {
    uint32_t a;
    asm("{ .reg .u64 t; cvta.to.shared.u64 t, %1; cvt.u32.u64 %0, t; }" : "=r"(a) : "l"(p));
    return a;
}
__device__ __forceinline__ uint32_t ctarank() {
    uint32_t r; asm("mov.u32 %0, %%cluster_ctarank;" : "=r"(r)); return r;
}
__device__ __forceinline__ uint32_t mapa_(uint32_t a, uint32_t rk) {
    uint32_t r; asm("mapa.shared::cluster.u32 %0, %1, %2;" : "=r"(r) : "r"(a), "r"(rk));
    return r;
}
__device__ __forceinline__ void stc(uint32_t a, float v) {
    asm volatile("st.shared::cluster.f32 [%0], %1;" :: "r"(a), "f"(v) : "memory");
}
__device__ __forceinline__ void cl_arrive() {
    asm volatile("barrier.cluster.arrive.aligned;" ::: "memory");
}
__device__ __forceinline__ void cl_wait() {
    asm volatile("barrier.cluster.wait.aligned;" ::: "memory");
}

__global__ void permute_weights(const float* __restrict__ W_ih, const float* __restrict__ W_hh,
                                const float* __restrict__ W1, const float* __restrict__ W2,
                                const float* __restrict__ Wz)
{
    const int stride = gridDim.x * blockDim.x;
    const int tid = blockIdx.x * blockDim.x + threadIdx.x;
    // band layout: row rr = rank*256 + g*64 + Rg  ->  global gate row g*256 + rank*64 + Rg
    for (int i = tid; i < KG4 * 1024 * 4; i += stride) {
        int j = i & 3, rr = (i >> 2) & 1023, k4 = i >> 12;
        int rank = rr >> 8, r = rr & 255;
        int G = ((r >> 6) << 8) + (rank << 6) + (r & 63);
        int k = 4 * k4 + j;
        Wg_perm[i] = (k < 40) ? W_ih[G * 40 + k] : W_hh[G * 256 + (k - 40)];
    }
    for (int i = tid; i < 64 * 128 * 4; i += stride) {
        int j = i & 3, m = (i >> 2) & 127, k4 = i >> 9;
        W1_perm[i] = W1[m * 256 + 4 * k4 + j];
    }
    for (int i = tid; i < 32 * 128 * 4; i += stride) {
        int j = i & 3, m = (i >> 2) & 127, k4 = i >> 9;
        W2_perm[i] = W2[m * 128 + 4 * k4 + j];
    }
    for (int i = tid; i < 32 * 64 * 4; i += stride) {
        int j = i & 3, m = (i >> 2) & 63, k4 = i >> 8;
        Wz_perm[i] = Wz[m * 128 + 4 * k4 + j];
    }
}

__global__ void __launch_bounds__(NT, 1) __cluster_dims__(CL, 1, 1)
lstm_guide_kernel(const float* __restrict__ A, const float* __restrict__ eps,
                  const float* __restrict__ z0, const float* __restrict__ h0,
                  const float* __restrict__ c0, const float* __restrict__ b_ih,
                  const float* __restrict__ b_hh, const float* __restrict__ b1,
                  const float* __restrict__ b2, const float* __restrict__ bz,
                  float* __restrict__ Z)
{
    extern __shared__ __align__(16) float smf[];
    float* xh  = smf + XH_F;   // cols: a 0..7 | z 8..39 | h 40..295
    float* u1s = smf + U1_F;
    float* u2s = smf + U2_F;
    float* zzs = smf + ZZ_F;

    const int tid = threadIdx.x;
    const uint32_t rank = ctarank();
    const int n0c = (blockIdx.x >> 2) * 32;
    const int Rg = tid >> 3, bg = tid & 7;
    const int hidG = 64 * (int)rank + Rg;

    const uint32_t smem0 = smem_u32(smf);

    // hoisted remote xh base addresses (both buffers, all 4 ranks)
    uint32_t xm[2][CL];
    #pragma unroll
    for (int g = 0; g < CL; ++g) {
        xm[0][g] = mapa_(smem0 + XH_F * 4, g);
        xm[1][g] = mapa_(smem0 + (XH_F + 32 * KGP) * 4, g);
    }

    const float bs0 = b_ih[hidG]       + b_hh[hidG];
    const float bs1 = b_ih[256 + hidG] + b_hh[256 + hidG];
    const float bs2 = b_ih[512 + hidG] + b_hh[512 + hidG];
    const float bs3 = b_ih[768 + hidG] + b_hh[768 + hidG];
    const float b1v = b1[tid >> 2], b2v = b2[tid >> 2], bzv = bz[tid >> 3];

    for (int i = tid; i < 32 * 256; i += NT) {          // h0
        int b = i >> 8, k = i & 255;
        xh[b * KGP + 40 + k] = h0[k];
    }
    for (int i = tid; i < 32 * ZD; i += NT) {           // z0
        int b = i >> 5, j = i & 31;
        xh[b * KGP + 8 + j] = z0[j];
    }
    if (tid < 256) {                                    // a_0
        int b = tid >> 3, k = tid & 7;
        xh[b * KGP + k] = A[((n0c + b) * TT) * AD + k];
    }
    float c_reg[4];
    #pragma unroll
    for (int j = 0; j < 4; ++j) c_reg[j] = c0[hidG];

    __syncthreads();
    cl_arrive(); cl_wait();

    const float* wb = Wg_perm + ((int)rank * 256 + Rg) * 4;

    for (int t = 0; t < TT; ++t) {
        const int cb = t & 1, nb = (t + 1) & 1;
        float* xh_p = xh + cb * 32 * KGP;
        float* xh_n = xh + nb * 32 * KGP;

        // ===== gates: 4 gate rows (i,f,g,o) of hidG  x  4 batch rows =====
        ull acc[4][4];
        #pragma unroll
        for (int g = 0; g < 4; ++g)
            #pragma unroll
            for (int j = 0; j < 4; ++j) acc[g][j] = 0ull;

        #pragma unroll 2
        for (int k4 = 0; k4 < KG4; ++k4) {
            const ulonglong2 w0 = __ldg((const ulonglong2*)(wb + (k4 * 1024 +   0) * 4));
            const ulonglong2 w1 = __ldg((const ulonglong2*)(wb + (k4 * 1024 +  64) * 4));
            const ulonglong2 w2 = __ldg((const ulonglong2*)(wb + (k4 * 1024 + 128) * 4));
            const ulonglong2 w3 = __ldg((const ulonglong2*)(wb + (k4 * 1024 + 192) * 4));
            #pragma unroll
            for (int j = 0; j < 4; ++j) {
                const ulonglong2 xv = *(const ulonglong2*)(xh_p + (bg + 8 * j) * KGP + 4 * k4);
                fma2(acc[0][j], w0.x, xv.x); fma2(acc[0][j], w0.y, xv.y);
                fma2(acc[1][j], w1.x, xv.x); fma2(acc[1][j], w1.y, xv.y);
                fma2(acc[2][j], w2.x, xv.x); fma2(acc[2][j], w2.y, xv.y);
                fma2(acc[3][j], w3.x, xv.x); fma2(acc[3][j], w3.y, xv.y);
            }
        }

        // ===== LSTM cell, all gates in-thread =====
        float hv[4];
        #pragma unroll
        for (int j = 0; j < 4; ++j) {
            float iv = fsig(hsum2(acc[0][j]) + bs0);
            float fv = fsig(hsum2(acc[1][j]) + bs1);
            float gv = ftanh_(hsum2(acc[2][j]) + bs2);
            float ov = fsig(hsum2(acc[3][j]) + bs3);
            float c = fv * c_reg[j] + iv * gv;
            c_reg[j] = c;
            hv[j] = ov * ftanh_(c);
        }

        // ===== h broadcast to all 4 CTAs' next xh; release via cluster arrive =====
        {
            const uint32_t hoff = (uint32_t)(40 + hidG) * 4;
            #pragma unroll
            for (int g = 0; g < CL; ++g) {
                const uint32_t base = xm[nb][g] + hoff;
                #pragma unroll
                for (int j = 0; j < 4; ++j)
                    stc(base + (uint32_t)((bg + 8 * j) * KGP) * 4, hv[j]);
            }
        }
        cl_arrive();

        if (tid < 256 && t + 1 < TT) {                  // a_{t+1} prefetch (local)
            int b = tid >> 3, k = tid & 7;
            xh_n[b * KGP + k] = A[((n0c + b) * TT + t + 1) * AD + k];
        }

        cl_wait();

        // ===== MLP1: relu(h_{t+1} @ W1^T + b1), own 8 batch rows =====
        {
            const int m = tid >> 2, bq = tid & 3;
            const float* x0 = xh_n + (8 * (int)rank + bq) * KGP + 40;
            const float* x1 = x0 + 4 * KGP;
            ull a0 = 0ull, a1 = 0ull;
            #pragma unroll 4
            for (int k4 = 0; k4 < 64; ++k4) {
                const ulonglong2 wv = __ldg((const ulonglong2*)(W1_perm + ((k4 << 7) + m) * 4));
                const ulonglong2 p0 = *(const ulonglong2*)(x0 + 4 * k4);
                const ulonglong2 p1 = *(const ulonglong2*)(x1 + 4 * k4);
                fma2(a0, wv.x, p0.x); fma2(a0, wv.y, p0.y);
                fma2(a1, wv.x, p1.x); fma2(a1, wv.y, p1.y);
            }
            u1s[bq * US + m]       = fmaxf(hsum2(a0) + b1v, 0.f);
            u1s[(bq + 4) * US + m] = fmaxf(hsum2(a1) + b1v, 0.f);
        }
        __syncthreads();

        // ===== MLP2 =====
        {
            const int m = tid >> 2, bq = tid & 3;
            const float* x0 = u1s + bq * US;
            const float* x1 = x0 + 4 * US;
            ull a0 = 0ull, a1 = 0ull;
            #pragma unroll 4
            for (int k4 = 0; k4 < 32; ++k4) {
                const ulonglong2 wv = __ldg((const ulonglong2*)(W2_perm + ((k4 << 7) + m) * 4));
                const ulonglong2 p0 = *(const ulonglong2*)(x0 + 4 * k4);
                const ulonglong2 p1 = *(const ulonglong2*)(x1 + 4 * k4);
                fma2(a0, wv.x, p0.x); fma2(a0, wv.y, p0.y);
                fma2(a1, wv.x, p1.x); fma2(a1, wv.y, p1.y);
            }
            u2s[bq * US + m]       = fmaxf(hsum2(a0) + b2v, 0.f);
            u2s[(bq + 4) * US + m] = fmaxf(hsum2(a1) + b2v, 0.f);
        }
        __syncthreads();

        // ===== zz = u2 @ Wz^T + bz =====
        {
            const int jz = tid >> 3, rz = tid & 7;
            const float* xp = u2s + rz * US;
            ull a0 = 0ull;
            #pragma unroll 4
            for (int k4 = 0; k4 < 32; ++k4) {
                const ulonglong2 wv = __ldg((const ulonglong2*)(Wz_perm + ((k4 << 6) + jz) * 4));
                const ulonglong2 pv = *(const ulonglong2*)(xp + 4 * k4);
                fma2(a0, wv.x, pv.x); fma2(a0, wv.y, pv.y);
            }
            zzs[rz * 64 + jz] = hsum2(a0) + bzv;
        }
        __syncthreads();

        // ===== z_t = loc + softplus(raw) * eps; broadcast to cluster =====
        if (tid < 256) {
            const int j = tid & 31, rr = tid >> 5;
            const int bown = 8 * (int)rank + rr;
            float loc = zzs[rr * 64 + j];
            float sr  = zzs[rr * 64 + 32 + j];
            float sp  = (sr > 15.f) ? sr : log1pf(__expf(sr));
            float e   = eps[((n0c + bown) * TT + t) * ZD + j];
            float zn  = fmaf(sp, e, loc);
            Z[((n0c + bown) * TT + t) * ZD + j] = zn;
            const uint32_t zoff = (uint32_t)((bown * KGP + 8 + j) * 4);
            #pragma unroll
            for (int g = 0; g < CL; ++g) stc(xm[nb][g] + zoff, zn);
        }
        cl_arrive(); cl_wait();
    }
}

extern "C" void kernel_launch(void* const* d_in, const int* in_sizes, int n_in,
                              void* d_out, int out_size) {
    const float* A    = (const float*)d_in[0];
    const float* eps  = (const float*)d_in[1];
    const float* z0   = (const float*)d_in[2];
    const float* h0   = (const float*)d_in[3];
    const float* c0   = (const float*)d_in[4];
    const float* W_ih = (const float*)d_in[5];
    const float* W_hh = (const float*)d_in[6];
    const float* b_ih = (const float*)d_in[7];
    const float* b_hh = (const float*)d_in[8];
    const float* W1   = (const float*)d_in[9];
    const float* b1   = (const float*)d_in[10];
    const float* W2   = (const float*)d_in[11];
    const float* b2   = (const float*)d_in[12];
    const float* Wz   = (const float*)d_in[13];
    const float* bz   = (const float*)d_in[14];

    static int smem_set = 0;
    if (!smem_set) {
        cudaFuncSetAttribute(lstm_guide_kernel,
                             cudaFuncAttributeMaxDynamicSharedMemorySize, SMEM_B);
        smem_set = 1;
    }
    permute_weights<<<148, 256>>>(W_ih, W_hh, W1, W2, Wz);
    lstm_guide_kernel<<<128, NT, SMEM_B>>>(A, eps, z0, h0, c0,
                                           b_ih, b_hh, b1, b2, bz, (float*)d_out);
}

// round 7
// speedup vs baseline: 1.4270x; 1.3628x over previous
#include <cuda_runtime.h>
typedef unsigned long long ull;

#define TT 128
#define ZD 32
#define KG4 74
#define KGP 300   // padded xh row stride (floats): a 0..7 | z 8..39 | h 40..295
#define US 132
#define NT 512

__device__ __align__(16) float Wg_perm[KG4 * 1024 * 4];  // [k4][1024 rows][4]
__device__ __align__(16) float W1_perm[64 * 128 * 4];
__device__ __align__(16) float W2_perm[32 * 128 * 4];
__device__ __align__(16) float Wz_perm[32 * 64 * 4];

__device__ __forceinline__ void fma2(ull &d, ull a, ull b) {
    asm("fma.rn.f32x2 %0, %1, %2, %0;" : "+l"(d) : "l"(a), "l"(b));
}
__device__ __forceinline__ float hsum2(ull v) {
    float lo, hi; asm("mov.b64 {%0, %1}, %2;" : "=f"(lo), "=f"(hi) : "l"(v));
    return lo + hi;
}
__device__ __forceinline__ float fsig(float x) { return 1.f / (1.f + __expf(-x)); }
__device__ __forceinline__ float ftanh_(float x) { return fmaf(2.f, fsig(2.f * x), -1.f); }

__global__ void permute_weights(const float* __restrict__ W_ih, const float* __restrict__ W_hh,
                                const float* __restrict__ W1, const float* __restrict__ W2,
                                const float* __restrict__ Wz)
{
    const int stride = gridDim.x * blockDim.x;
    const int tid = blockIdx.x * blockDim.x + threadIdx.x;
    for (int i = tid; i < KG4 * 1024 * 4; i += stride) {
        int j = i & 3, R = (i >> 2) & 1023, k4 = i >> 12;
        int k = 4 * k4 + j;
        Wg_perm[i] = (k < 40) ? W_ih[R * 40 + k] : W_hh[R * 256 + (k - 40)];
    }
    for (int i = tid; i < 64 * 128 * 4; i += stride) {
        int j = i & 3, m = (i >> 2) & 127, k4 = i >> 9;
        W1_perm[i] = W1[m * 256 + 4 * k4 + j];
    }
    for (int i = tid; i < 32 * 128 * 4; i += stride) {
        int j = i & 3, m = (i >> 2) & 127, k4 = i >> 9;
        W2_perm[i] = W2[m * 128 + 4 * k4 + j];
    }
    for (int i = tid; i < 32 * 64 * 4; i += stride) {
        int j = i & 3, m = (i >> 2) & 63, k4 = i >> 8;
        Wz_perm[i] = Wz[m * 128 + 4 * k4 + j];
    }
}

// One CTA = 8 batch rows, 512 threads. Thread (hid=tid>>1, bq=tid&1) computes
// all 4 gates of `hid` for 4 batch rows b=bq*4+j. 8 mem instr / 32 FMA2.
__global__ void __launch_bounds__(NT, 1)
lstm_guide_kernel(const float* __restrict__ A, const float* __restrict__ eps,
                  const float* __restrict__ z0, const float* __restrict__ h0,
                  const float* __restrict__ c0, const float* __restrict__ b_ih,
                  const float* __restrict__ b_hh, const float* __restrict__ b1,
                  const float* __restrict__ b2, const float* __restrict__ bz,
                  float* __restrict__ Z)
{
    __shared__ __align__(16) float xh[8 * KGP];
    __shared__ __align__(16) float u1s[8 * US];
    __shared__ __align__(16) float u2s[8 * US];
    __shared__ __align__(16) float zzs[8 * 64];

    const int tid = threadIdx.x;
    const int n0 = blockIdx.x * 8;
    const int hid = tid >> 1, bq = tid & 1;

    const float bs0 = b_ih[hid]       + b_hh[hid];
    const float bs1 = b_ih[256 + hid] + b_hh[256 + hid];
    const float bs2 = b_ih[512 + hid] + b_hh[512 + hid];
    const float bs3 = b_ih[768 + hid] + b_hh[768 + hid];
    const float b1v = b1[tid & 127], b2v = b2[tid & 127], bzv = bz[tid & 63];

    for (int i = tid; i < 8 * 256; i += NT) {       // h0
        int b = i >> 8, k = i & 255;
        xh[b * KGP + 40 + k] = h0[k];
    }
    if (tid < 64) {                                 // a_0
        int b = tid >> 3, k = tid & 7;
        xh[b * KGP + k] = A[((n0 + b) * TT) * 8 + k];
    } else if (tid < 320) {                         // z_0
        int i = tid - 64, b = i >> 5, j = i & 31;
        xh[b * KGP + 8 + j] = z0[j];
    }
    float c_reg[4];
    #pragma unroll
    for (int j = 0; j < 4; ++j) c_reg[j] = c0[hid];
    __syncthreads();

    const float* wb = Wg_perm + hid * 4;

    for (int t = 0; t < TT; ++t) {
        // ===== gates: 4 rows (i,f,g,o of hid) x 4 batch (b = bq*4+j) =====
        ull acc[4][4];
        #pragma unroll
        for (int g = 0; g < 4; ++g)
            #pragma unroll
            for (int j = 0; j < 4; ++j) acc[g][j] = 0ull;

        #pragma unroll 2
        for (int k4 = 0; k4 < KG4; ++k4) {
            const ulonglong2 w0 = __ldg((const ulonglong2*)(wb + (k4 * 1024 +   0) * 4));
            const ulonglong2 w1 = __ldg((const ulonglong2*)(wb + (k4 * 1024 + 256) * 4));
            const ulonglong2 w2 = __ldg((const ulonglong2*)(wb + (k4 * 1024 + 512) * 4));
            const ulonglong2 w3 = __ldg((const ulonglong2*)(wb + (k4 * 1024 + 768) * 4));
            #pragma unroll
            for (int j = 0; j < 4; ++j) {
                const ulonglong2 xv = *(const ulonglong2*)(xh + (bq * 4 + j) * KGP + 4 * k4);
                fma2(acc[0][j], w0.x, xv.x); fma2(acc[0][j], w0.y, xv.y);
                fma2(acc[1][j], w1.x, xv.x); fma2(acc[1][j], w1.y, xv.y);
                fma2(acc[2][j], w2.x, xv.x); fma2(acc[2][j], w2.y, xv.y);
                fma2(acc[3][j], w3.x, xv.x); fma2(acc[3][j], w3.y, xv.y);
            }
        }

        // ===== LSTM cell, all gates in-thread =====
        float hv[4];
        #pragma unroll
        for (int j = 0; j < 4; ++j) {
            float iv = fsig(hsum2(acc[0][j]) + bs0);
            float fv = fsig(hsum2(acc[1][j]) + bs1);
            float gv = ftanh_(hsum2(acc[2][j]) + bs2);
            float ov = fsig(hsum2(acc[3][j]) + bs3);
            float c = fv * c_reg[j] + iv * gv;
            c_reg[j] = c;
            hv[j] = ov * ftanh_(c);
        }
        __syncthreads();   // gate reads of xh done everywhere

        // write h_{t+1}; prefetch a_{t+1}
        #pragma unroll
        for (int j = 0; j < 4; ++j)
            xh[(bq * 4 + j) * KGP + 40 + hid] = hv[j];
        if (tid < 64 && t + 1 < TT) {
            int b = tid >> 3, k = tid & 7;
            xh[b * KGP + k] = A[((n0 + b) * TT + t + 1) * 8 + k];
        }
        __syncthreads();

        // ===== MLP1: relu(h @ W1^T + b1) =====
        {
            const int m = tid & 127, q = tid >> 7;
            const float* x0 = xh + (2 * q) * KGP + 40;
            const float* x1 = x0 + KGP;
            ull a0 = 0ull, a1 = 0ull;
            #pragma unroll 4
            for (int k4 = 0; k4 < 64; ++k4) {
                const ulonglong2 wv = __ldg((const ulonglong2*)(W1_perm + ((k4 << 7) + m) * 4));
                const ulonglong2 p0 = *(const ulonglong2*)(x0 + 4 * k4);
                const ulonglong2 p1 = *(const ulonglong2*)(x1 + 4 * k4);
                fma2(a0, wv.x, p0.x); fma2(a0, wv.y, p0.y);
                fma2(a1, wv.x, p1.x); fma2(a1, wv.y, p1.y);
            }
            u1s[(2 * q) * US + m]     = fmaxf(hsum2(a0) + b1v, 0.f);
            u1s[(2 * q + 1) * US + m] = fmaxf(hsum2(a1) + b1v, 0.f);
        }
        __syncthreads();

        // ===== MLP2 =====
        {
            const int m = tid & 127, q = tid >> 7;
            const float* x0 = u1s + (2 * q) * US;
            const float* x1 = x0 + US;
            ull a0 = 0ull, a1 = 0ull;
            #pragma unroll 4
            for (int k4 = 0; k4 < 32; ++k4) {
                const ulonglong2 wv = __ldg((const ulonglong2*)(W2_perm + ((k4 << 7) + m) * 4));
                const ulonglong2 p0 = *(const ulonglong2*)(x0 + 4 * k4);
                const ulonglong2 p1 = *(const ulonglong2*)(x1 + 4 * k4);
                fma2(a0, wv.x, p0.x); fma2(a0, wv.y, p0.y);
                fma2(a1, wv.x, p1.x); fma2(a1, wv.y, p1.y);
            }
            u2s[(2 * q) * US + m]     = fmaxf(hsum2(a0) + b2v, 0.f);
            u2s[(2 * q + 1) * US + m] = fmaxf(hsum2(a1) + b2v, 0.f);
        }
        __syncthreads();

        // ===== zz = u2 @ Wz^T + bz =====
        {
            const int jz = tid & 63, rz = tid >> 6;
            const float* xp = u2s + rz * US;
            ull a0 = 0ull;
            #pragma unroll 4
            for (int k4 = 0; k4 < 32; ++k4) {
                const ulonglong2 wv = __ldg((const ulonglong2*)(Wz_perm + ((k4 << 6) + jz) * 4));
                const ulonglong2 pv = *(const ulonglong2*)(xp + 4 * k4);
                fma2(a0, wv.x, pv.x); fma2(a0, wv.y, pv.y);
            }
            zzs[rz * 64 + jz] = hsum2(a0) + bzv;
        }
        __syncthreads();

        // ===== z_t = loc + softplus(raw) * eps =====
        if (tid < 256) {
            const int j = tid & 31, r = tid >> 5;
            float loc = zzs[r * 64 + j];
            float sr  = zzs[r * 64 + 32 + j];
            float sp  = (sr > 15.f) ? sr : log1pf(__expf(sr));
            float e   = eps[((n0 + r) * TT + t) * ZD + j];
            float zn  = fmaf(sp, e, loc);
            Z[((n0 + r) * TT + t) * ZD + j] = zn;
            xh[r * KGP + 8 + j] = zn;
        }
        __syncthreads();
    }
}

extern "C" void kernel_launch(void* const* d_in, const int* in_sizes, int n_in,
                              void* d_out, int out_size) {
    const float* A    = (const float*)d_in[0];
    const float* eps  = (const float*)d_in[1];
    const float* z0   = (const float*)d_in[2];
    const float* h0   = (const float*)d_in[3];
    const float* c0   = (const float*)d_in[4];
    const float* W_ih = (const float*)d_in[5];
    const float* W_hh = (const float*)d_in[6];
    const float* b_ih = (const float*)d_in[7];
    const float* b_hh = (const float*)d_in[8];
    const float* W1   = (const float*)d_in[9];
    const float* b1   = (const float*)d_in[10];
    const float* W2   = (const float*)d_in[11];
    const float* b2   = (const float*)d_in[12];
    const float* Wz   = (const float*)d_in[13];
    const float* bz   = (const float*)d_in[14];

    permute_weights<<<148, 256>>>(W_ih, W_hh, W1, W2, Wz);
    lstm_guide_kernel<<<128, NT>>>(A, eps, z0, h0, c0,
                                   b_ih, b_hh, b1, b2, bz, (float*)d_out);
}